// round 9
// baseline (speedup 1.0000x reference)
#include <cuda_runtime.h>
#include <cuda_fp16.h>
#include <cstdint>

#define TOK 4096
#define DIM 1024
#define NEXP 8
#define HID 2816
#define ALIGNM 128
#define MAXSLOTS (TOK*2 + NEXP*ALIGNM)   // 9216
#define MTILES (MAXSLOTS/128)            // 72
#define WELEM (NEXP*HID*DIM)             // 23068672

__device__ __half g_Xph[(size_t)MAXSLOTS * DIM];
__device__ __half g_Hh [(size_t)MAXSLOTS * HID];
__device__ float  g_O  [(size_t)MAXSLOTS * DIM];
__device__ __half g_W1h[(size_t)WELEM];
__device__ __half g_W2h[(size_t)WELEM];
__device__ __half g_W3h[(size_t)WELEM];
__device__ int    g_cnt[NEXP];
__device__ int    g_aoff[NEXP + 1];
__device__ int    g_cur[NEXP];
__device__ int    g_ei[TOK * 2];
__device__ float  g_ew[TOK * 2];
__device__ int    g_slot_token[MAXSLOTS];
__device__ int    g_slot_of[TOK * 2];

// ---- helpers ----
__device__ __forceinline__ void ldm4(uint32_t* r, uint32_t addr) {
    asm volatile("ldmatrix.sync.aligned.m8n8.x4.shared.b16 {%0,%1,%2,%3}, [%4];"
        : "=r"(r[0]), "=r"(r[1]), "=r"(r[2]), "=r"(r[3]) : "r"(addr));
}
__device__ __forceinline__ void mma16816(float* c, const uint32_t* a, const uint32_t* b) {
    asm volatile("mma.sync.aligned.m16n8k16.row.col.f32.f16.f16.f32 "
        "{%0,%1,%2,%3}, {%4,%5,%6,%7}, {%8,%9}, {%0,%1,%2,%3};"
        : "+f"(c[0]), "+f"(c[1]), "+f"(c[2]), "+f"(c[3])
        : "r"(a[0]), "r"(a[1]), "r"(a[2]), "r"(a[3]), "r"(b[0]), "r"(b[1]));
}
__device__ __forceinline__ void cpa16(uint32_t saddr, const void* g) {
    asm volatile("cp.async.cg.shared.global [%0], [%1], 16;" :: "r"(saddr), "l"(g));
}
__device__ __forceinline__ void cpa_commit() { asm volatile("cp.async.commit_group;"); }
template <int N>
__device__ __forceinline__ void cpa_wait() { asm volatile("cp.async.wait_group %0;" :: "n"(N)); }

// ---------------- setup kernels ----------------
__global__ void k_zero() { if (threadIdx.x < NEXP) g_cnt[threadIdx.x] = 0; }

__global__ void k_cvt(const float* __restrict__ src, __half* __restrict__ dst, int n4) {
    int i = blockIdx.x * blockDim.x + threadIdx.x;
    if (i >= n4) return;
    float4 v = ((const float4*)src)[i];
    __half2 h0 = __floats2half2_rn(v.x, v.y);
    __half2 h1 = __floats2half2_rn(v.z, v.w);
    uint2 u; u.x = *(uint32_t*)&h0; u.y = *(uint32_t*)&h1;
    ((uint2*)dst)[i] = u;
}

__global__ void k_gate(const float* __restrict__ x, const float* __restrict__ gw) {
    int t = blockIdx.x * 8 + (threadIdx.x >> 5);
    int lane = threadIdx.x & 31;
    if (t >= TOK) return;
    const float* xr = x + (size_t)t * DIM;
    float acc[NEXP];
#pragma unroll
    for (int e = 0; e < NEXP; e++) acc[e] = 0.f;
    for (int i = lane; i < DIM; i += 32) {
        float xv = xr[i];
#pragma unroll
        for (int e = 0; e < NEXP; e++) acc[e] += xv * gw[e * DIM + i];
    }
#pragma unroll
    for (int e = 0; e < NEXP; e++)
#pragma unroll
        for (int o = 16; o; o >>= 1) acc[e] += __shfl_xor_sync(0xFFFFFFFFu, acc[e], o);
    if (lane == 0) {
        float m = acc[0];
#pragma unroll
        for (int e = 1; e < NEXP; e++) m = fmaxf(m, acc[e]);
        float p[NEXP];
#pragma unroll
        for (int e = 0; e < NEXP; e++) p[e] = __expf(acc[e] - m);
        int i0 = 0;
#pragma unroll
        for (int e = 1; e < NEXP; e++) if (p[e] > p[i0]) i0 = e;
        int i1 = (i0 == 0) ? 1 : 0;
#pragma unroll
        for (int e = 0; e < NEXP; e++) if (e != i0 && p[e] > p[i1]) i1 = e;
        float w0 = p[i0], w1 = p[i1], inv = 1.f / (w0 + w1);
        g_ei[t*2] = i0; g_ei[t*2+1] = i1;
        g_ew[t*2] = w0*inv; g_ew[t*2+1] = w1*inv;
        atomicAdd(&g_cnt[i0], 1);
        atomicAdd(&g_cnt[i1], 1);
    }
}

__global__ void k_scan() {
    if (threadIdx.x == 0) {
        int acc = 0;
        for (int e = 0; e < NEXP; e++) {
            g_aoff[e] = acc; g_cur[e] = acc;
            acc += (g_cnt[e] + ALIGNM - 1) & ~(ALIGNM - 1);
        }
        g_aoff[NEXP] = acc;
    }
    for (int i = threadIdx.x; i < MAXSLOTS; i += blockDim.x) g_slot_token[i] = 0;
}

__global__ void k_scatter() {
    int t = blockIdx.x * blockDim.x + threadIdx.x;
    if (t >= TOK) return;
#pragma unroll
    for (int k = 0; k < 2; k++) {
        int e = g_ei[t*2+k];
        int pos = atomicAdd(&g_cur[e], 1);
        g_slot_token[pos] = t;
        g_slot_of[t*2+k] = pos;
    }
}

__global__ void k_permute(const float* __restrict__ x) {
    int slot = blockIdx.x;
    int tok = g_slot_token[slot];
    float4 v = ((const float4*)(x + (size_t)tok * DIM))[threadIdx.x];
    __half2 h0 = __floats2half2_rn(v.x, v.y);
    __half2 h1 = __floats2half2_rn(v.z, v.w);
    uint2 u; u.x = *(uint32_t*)&h0; u.y = *(uint32_t*)&h1;
    ((uint2*)(g_Xph + (size_t)slot * DIM))[threadIdx.x] = u;
}

// ---------------- GEMM1: H = silu(X W1^T)*(X W3^T) ----------------
// BM=128, BN=128, BK=64. 512 thr, 16 warps 4x4, warp tile 32x32.
// smem per stage: A 16K + B1 16K + B3 16K = 48K; 3 stages = 144K (dynamic).
// Row = 128B = 8 chunks of 16B, swizzle: chunk' = chunk ^ (row & 7).
#define S1_A  0
#define S1_B1 16384
#define S1_B3 32768
#define S1_STG 49152
#define S1_SMEM (3 * S1_STG)

__global__ __launch_bounds__(512, 1) void k_gemm1(const __half* __restrict__ W1g,
                                                  const __half* __restrict__ W3g) {
    extern __shared__ __align__(1024) uint8_t smem[];
    const int m0 = blockIdx.x * 128;
    if (m0 >= g_aoff[NEXP]) return;
    int e = 0;
    while (m0 >= g_aoff[e + 1]) e++;
    const int n0 = blockIdx.y * 128;
    const __half* W1 = W1g + (size_t)e * HID * DIM;
    const __half* W3 = W3g + (size_t)e * HID * DIM;

    const int tid = threadIdx.x, wid = tid >> 5, lane = tid & 31;
    const int wm = wid & 3, wn = wid >> 2;
    const uint32_t smemB = (uint32_t)__cvta_generic_to_shared(smem);

    // cp.async coords: 2 chunks per thread per matrix region
    int arow[2], ach[2];
    const __half* agp[2];
    const __half* b1gp[2];
    const __half* b3gp[2];
    uint32_t asw[2], bsw[2];
#pragma unroll
    for (int i = 0; i < 2; i++) {
        int idx = tid + i * 512;
        int row = idx >> 3, ch = idx & 7;
        arow[i] = row; ach[i] = ch;
        agp[i]  = g_Xph + (size_t)(m0 + row) * DIM + ch * 8;
        b1gp[i] = W1 + (size_t)(n0 + row) * DIM + ch * 8;
        b3gp[i] = W3 + (size_t)(n0 + row) * DIM + ch * 8;
        uint32_t off = (uint32_t)row * 128 + (uint32_t)((ch ^ (row & 7)) << 4);
        asw[i] = off; bsw[i] = off;
    }
    auto prefetch = [&](int t) {
        uint32_t st = smemB + (uint32_t)(t % 3) * S1_STG;
        const int k0 = t * 64;
#pragma unroll
        for (int i = 0; i < 2; i++) {
            cpa16(st + S1_A  + asw[i], agp[i]  + k0);
            cpa16(st + S1_B1 + bsw[i], b1gp[i] + k0);
            cpa16(st + S1_B3 + bsw[i], b3gp[i] + k0);
        }
    };

    // ldmatrix coords (fragment math identical to validated round-7 kernel)
    const int sub = lane >> 3, rin = lane & 7;
    const int asel = sub >> 1, bsel = sub & 1;
    uint32_t arow128[2], brow128[2];
#pragma unroll
    for (int mi = 0; mi < 2; mi++)
        arow128[mi] = (uint32_t)(wm * 32 + mi * 16 + (sub & 1) * 8 + rin) * 128;
#pragma unroll
    for (int nh = 0; nh < 2; nh++)
        brow128[nh] = (uint32_t)(wn * 32 + nh * 16 + (sub >> 1) * 8 + rin) * 128;

    float c1[2][4][4], c3[2][4][4];
#pragma unroll
    for (int mi = 0; mi < 2; mi++)
#pragma unroll
        for (int ni = 0; ni < 4; ni++)
#pragma unroll
            for (int q = 0; q < 4; q++) { c1[mi][ni][q] = 0.f; c3[mi][ni][q] = 0.f; }

    const int KT = DIM / 64;   // 16
    prefetch(0); cpa_commit();
    prefetch(1); cpa_commit();

#pragma unroll 1
    for (int t = 0; t < KT; t++) {
        cpa_wait<1>();
        __syncthreads();
        if (t + 2 < KT) prefetch(t + 2);
        cpa_commit();
        const uint32_t smb = smemB + (uint32_t)(t % 3) * S1_STG;
#pragma unroll
        for (int ks = 0; ks < 4; ks++) {
            const uint32_t axo = (uint32_t)(((2 * ks + asel) ^ rin) << 4);
            const uint32_t bxo = (uint32_t)(((2 * ks + bsel) ^ rin) << 4);
            uint32_t a[2][4], b1[2][4], b3[2][4];
#pragma unroll
            for (int mi = 0; mi < 2; mi++) ldm4(a[mi], smb + S1_A + arow128[mi] + axo);
#pragma unroll
            for (int nh = 0; nh < 2; nh++) {
                ldm4(b1[nh], smb + S1_B1 + brow128[nh] + bxo);
                ldm4(b3[nh], smb + S1_B3 + brow128[nh] + bxo);
            }
#pragma unroll
            for (int mi = 0; mi < 2; mi++)
#pragma unroll
                for (int ni = 0; ni < 4; ni++) {
                    mma16816(c1[mi][ni], a[mi], &b1[ni >> 1][2 * (ni & 1)]);
                    mma16816(c3[mi][ni], a[mi], &b3[ni >> 1][2 * (ni & 1)]);
                }
        }
    }

    // epilogue: h = silu(c1)*c3 -> fp16
    const int g = lane >> 2, tq = lane & 3;
#pragma unroll
    for (int mi = 0; mi < 2; mi++)
#pragma unroll
        for (int ni = 0; ni < 4; ni++) {
            int col = n0 + wn * 32 + ni * 8 + tq * 2;
#pragma unroll
            for (int h = 0; h < 2; h++) {
                int row = m0 + wm * 32 + mi * 16 + g + h * 8;
                float v0 = c1[mi][ni][h * 2], v1 = c1[mi][ni][h * 2 + 1];
                float s0 = v0 / (1.f + __expf(-v0)) * c3[mi][ni][h * 2];
                float s1 = v1 / (1.f + __expf(-v1)) * c3[mi][ni][h * 2 + 1];
                *(__half2*)(g_Hh + (size_t)row * HID + col) = __floats2half2_rn(s0, s1);
            }
        }
}

// ---------------- GEMM2: O = H W2^T ----------------
#define S2_A  0
#define S2_B  16384
#define S2_STG 32768
#define S2_SMEM (3 * S2_STG)

__global__ __launch_bounds__(512, 1) void k_gemm2(const __half* __restrict__ W2g) {
    extern __shared__ __align__(1024) uint8_t smem[];
    const int m0 = blockIdx.x * 128;
    if (m0 >= g_aoff[NEXP]) return;
    int e = 0;
    while (m0 >= g_aoff[e + 1]) e++;
    const int n0 = blockIdx.y * 128;
    const __half* W = W2g + (size_t)e * DIM * HID;

    const int tid = threadIdx.x, wid = tid >> 5, lane = tid & 31;
    const int wm = wid & 3, wn = wid >> 2;
    const uint32_t smemB = (uint32_t)__cvta_generic_to_shared(smem);

    const __half* agp[2];
    const __half* bgp[2];
    uint32_t sw[2];
#pragma unroll
    for (int i = 0; i < 2; i++) {
        int idx = tid + i * 512;
        int row = idx >> 3, ch = idx & 7;
        agp[i] = g_Hh + (size_t)(m0 + row) * HID + ch * 8;
        bgp[i] = W + (size_t)(n0 + row) * HID + ch * 8;
        sw[i] = (uint32_t)row * 128 + (uint32_t)((ch ^ (row & 7)) << 4);
    }
    auto prefetch = [&](int t) {
        uint32_t st = smemB + (uint32_t)(t % 3) * S2_STG;
        const int k0 = t * 64;
#pragma unroll
        for (int i = 0; i < 2; i++) {
            cpa16(st + S2_A + sw[i], agp[i] + k0);
            cpa16(st + S2_B + sw[i], bgp[i] + k0);
        }
    };

    const int sub = lane >> 3, rin = lane & 7;
    const int asel = sub >> 1, bsel = sub & 1;
    uint32_t arow128[2], brow128[2];
#pragma unroll
    for (int mi = 0; mi < 2; mi++)
        arow128[mi] = (uint32_t)(wm * 32 + mi * 16 + (sub & 1) * 8 + rin) * 128;
#pragma unroll
    for (int nh = 0; nh < 2; nh++)
        brow128[nh] = (uint32_t)(wn * 32 + nh * 16 + (sub >> 1) * 8 + rin) * 128;

    float c[2][4][4];
#pragma unroll
    for (int mi = 0; mi < 2; mi++)
#pragma unroll
        for (int ni = 0; ni < 4; ni++)
#pragma unroll
            for (int q = 0; q < 4; q++) c[mi][ni][q] = 0.f;

    const int KT = HID / 64;   // 44
    prefetch(0); cpa_commit();
    prefetch(1); cpa_commit();

#pragma unroll 1
    for (int t = 0; t < KT; t++) {
        cpa_wait<1>();
        __syncthreads();
        if (t + 2 < KT) prefetch(t + 2);
        cpa_commit();
        const uint32_t smb = smemB + (uint32_t)(t % 3) * S2_STG;
#pragma unroll
        for (int ks = 0; ks < 4; ks++) {
            const uint32_t axo = (uint32_t)(((2 * ks + asel) ^ rin) << 4);
            const uint32_t bxo = (uint32_t)(((2 * ks + bsel) ^ rin) << 4);
            uint32_t a[2][4], b[2][4];
#pragma unroll
            for (int mi = 0; mi < 2; mi++) ldm4(a[mi], smb + S2_A + arow128[mi] + axo);
#pragma unroll
            for (int nh = 0; nh < 2; nh++) ldm4(b[nh], smb + S2_B + brow128[nh] + bxo);
#pragma unroll
            for (int mi = 0; mi < 2; mi++)
#pragma unroll
                for (int ni = 0; ni < 4; ni++)
                    mma16816(c[mi][ni], a[mi], &b[ni >> 1][2 * (ni & 1)]);
        }
    }

    const int g = lane >> 2, tq = lane & 3;
#pragma unroll
    for (int mi = 0; mi < 2; mi++)
#pragma unroll
        for (int ni = 0; ni < 4; ni++) {
            int col = n0 + wn * 32 + ni * 8 + tq * 2;
#pragma unroll
            for (int h = 0; h < 2; h++) {
                int row = m0 + wm * 32 + mi * 16 + g + h * 8;
                float2 v = make_float2(c[mi][ni][h * 2], c[mi][ni][h * 2 + 1]);
                *(float2*)(g_O + (size_t)row * DIM + col) = v;
            }
        }
}

__global__ void k_combine(float* __restrict__ out) {
    int idx = blockIdx.x * blockDim.x + threadIdx.x;
    if (idx >= TOK * DIM / 4) return;
    int t = idx / (DIM / 4), d4 = idx % (DIM / 4);
    float w0 = g_ew[t*2], w1 = g_ew[t*2+1];
    int s0 = g_slot_of[t*2], s1 = g_slot_of[t*2+1];
    float4 a = *(const float4*)&g_O[(size_t)s0 * DIM + d4*4];
    float4 b = *(const float4*)&g_O[(size_t)s1 * DIM + d4*4];
    float4 r;
    r.x = w0*a.x + w1*b.x; r.y = w0*a.y + w1*b.y;
    r.z = w0*a.z + w1*b.z; r.w = w0*a.w + w1*b.w;
    ((float4*)out)[idx] = r;
}

extern "C" void kernel_launch(void* const* d_in, const int* in_sizes, int n_in,
                              void* d_out, int out_size) {
    const float* x  = (const float*)d_in[0];
    const float* gw = (const float*)d_in[1];
    const float* w1 = (const float*)d_in[2];
    const float* w2 = (const float*)d_in[3];
    const float* w3 = (const float*)d_in[4];
    float* out = (float*)d_out;

    cudaFuncSetAttribute(k_gemm1, cudaFuncAttributeMaxDynamicSharedMemorySize, S1_SMEM);
    cudaFuncSetAttribute(k_gemm2, cudaFuncAttributeMaxDynamicSharedMemorySize, S2_SMEM);

    __half *w1h, *w2h, *w3h;
    cudaGetSymbolAddress((void**)&w1h, g_W1h);
    cudaGetSymbolAddress((void**)&w2h, g_W2h);
    cudaGetSymbolAddress((void**)&w3h, g_W3h);

    const int N4 = WELEM / 4;   // 5767168
    k_cvt<<<(N4 + 255) / 256, 256>>>(w1, w1h, N4);
    k_cvt<<<(N4 + 255) / 256, 256>>>(w2, w2h, N4);
    k_cvt<<<(N4 + 255) / 256, 256>>>(w3, w3h, N4);

    k_zero<<<1, 32>>>();
    k_gate<<<TOK / 8, 256>>>(x, gw);
    k_scan<<<1, 256>>>();
    k_scatter<<<TOK / 256, 256>>>();
    k_permute<<<MAXSLOTS, 256>>>(x);
    k_gemm1<<<dim3(MTILES, HID / 128), 512, S1_SMEM>>>(w1h, w3h);
    k_gemm2<<<dim3(MTILES, DIM / 128), 512, S2_SMEM>>>(w2h);
    k_combine<<<(TOK * DIM / 4) / 256, 256>>>(out);
}

// round 10
// speedup vs baseline: 1.0001x; 1.0001x over previous
#include <cuda_runtime.h>
#include <cuda_fp16.h>
#include <cstdint>

#define TOK 4096
#define DIM 1024
#define NEXP 8
#define HID 2816
#define ALIGNM 128
#define MAXSLOTS (TOK*2 + NEXP*ALIGNM)   // 9216
#define MTILES (MAXSLOTS/128)            // 72
#define WELEM (NEXP*HID*DIM)             // 23068672

__device__ __half g_Xph[(size_t)MAXSLOTS * DIM];
__device__ __half g_Hh [(size_t)MAXSLOTS * HID];
__device__ float  g_O  [(size_t)MAXSLOTS * DIM];
__device__ __half g_W1h[(size_t)WELEM];
__device__ __half g_W2h[(size_t)WELEM];
__device__ __half g_W3h[(size_t)WELEM];
__device__ int    g_cnt[NEXP];
__device__ int    g_aoff[NEXP + 1];
__device__ int    g_cur[NEXP];
__device__ int    g_ei[TOK * 2];
__device__ float  g_ew[TOK * 2];
__device__ int    g_slot_token[MAXSLOTS];
__device__ int    g_slot_of[TOK * 2];

// ---- helpers ----
__device__ __forceinline__ void ldm4(uint32_t* r, uint32_t addr) {
    asm volatile("ldmatrix.sync.aligned.m8n8.x4.shared.b16 {%0,%1,%2,%3}, [%4];"
        : "=r"(r[0]), "=r"(r[1]), "=r"(r[2]), "=r"(r[3]) : "r"(addr));
}
__device__ __forceinline__ void mma16816(float* c, const uint32_t* a, const uint32_t* b) {
    asm volatile("mma.sync.aligned.m16n8k16.row.col.f32.f16.f16.f32 "
        "{%0,%1,%2,%3}, {%4,%5,%6,%7}, {%8,%9}, {%0,%1,%2,%3};"
        : "+f"(c[0]), "+f"(c[1]), "+f"(c[2]), "+f"(c[3])
        : "r"(a[0]), "r"(a[1]), "r"(a[2]), "r"(a[3]), "r"(b[0]), "r"(b[1]));
}
__device__ __forceinline__ void cpa16(uint32_t saddr, const void* g) {
    asm volatile("cp.async.cg.shared.global [%0], [%1], 16;" :: "r"(saddr), "l"(g));
}
__device__ __forceinline__ void cpa_commit() { asm volatile("cp.async.commit_group;"); }
template <int N>
__device__ __forceinline__ void cpa_wait() { asm volatile("cp.async.wait_group %0;" :: "n"(N)); }

// ---------------- setup kernels ----------------
__global__ void k_zero() { if (threadIdx.x < NEXP) g_cnt[threadIdx.x] = 0; }

__global__ void k_cvt(const float* __restrict__ src, __half* __restrict__ dst, int n4) {
    int i = blockIdx.x * blockDim.x + threadIdx.x;
    if (i >= n4) return;
    float4 v = ((const float4*)src)[i];
    __half2 h0 = __floats2half2_rn(v.x, v.y);
    __half2 h1 = __floats2half2_rn(v.z, v.w);
    uint2 u; u.x = *(uint32_t*)&h0; u.y = *(uint32_t*)&h1;
    ((uint2*)dst)[i] = u;
}

__global__ void k_gate(const float* __restrict__ x, const float* __restrict__ gw) {
    int t = blockIdx.x * 8 + (threadIdx.x >> 5);
    int lane = threadIdx.x & 31;
    if (t >= TOK) return;
    const float* xr = x + (size_t)t * DIM;
    float acc[NEXP];
#pragma unroll
    for (int e = 0; e < NEXP; e++) acc[e] = 0.f;
    for (int i = lane; i < DIM; i += 32) {
        float xv = xr[i];
#pragma unroll
        for (int e = 0; e < NEXP; e++) acc[e] += xv * gw[e * DIM + i];
    }
#pragma unroll
    for (int e = 0; e < NEXP; e++)
#pragma unroll
        for (int o = 16; o; o >>= 1) acc[e] += __shfl_xor_sync(0xFFFFFFFFu, acc[e], o);
    if (lane == 0) {
        float m = acc[0];
#pragma unroll
        for (int e = 1; e < NEXP; e++) m = fmaxf(m, acc[e]);
        float p[NEXP];
#pragma unroll
        for (int e = 0; e < NEXP; e++) p[e] = __expf(acc[e] - m);
        int i0 = 0;
#pragma unroll
        for (int e = 1; e < NEXP; e++) if (p[e] > p[i0]) i0 = e;
        int i1 = (i0 == 0) ? 1 : 0;
#pragma unroll
        for (int e = 0; e < NEXP; e++) if (e != i0 && p[e] > p[i1]) i1 = e;
        float w0 = p[i0], w1 = p[i1], inv = 1.f / (w0 + w1);
        g_ei[t*2] = i0; g_ei[t*2+1] = i1;
        g_ew[t*2] = w0*inv; g_ew[t*2+1] = w1*inv;
        atomicAdd(&g_cnt[i0], 1);
        atomicAdd(&g_cnt[i1], 1);
    }
}

__global__ void k_scan() {
    if (threadIdx.x == 0) {
        int acc = 0;
        for (int e = 0; e < NEXP; e++) {
            g_aoff[e] = acc; g_cur[e] = acc;
            acc += (g_cnt[e] + ALIGNM - 1) & ~(ALIGNM - 1);
        }
        g_aoff[NEXP] = acc;
    }
    for (int i = threadIdx.x; i < MAXSLOTS; i += blockDim.x) g_slot_token[i] = 0;
}

__global__ void k_scatter() {
    int t = blockIdx.x * blockDim.x + threadIdx.x;
    if (t >= TOK) return;
#pragma unroll
    for (int k = 0; k < 2; k++) {
        int e = g_ei[t*2+k];
        int pos = atomicAdd(&g_cur[e], 1);
        g_slot_token[pos] = t;
        g_slot_of[t*2+k] = pos;
    }
}

__global__ void k_permute(const float* __restrict__ x) {
    int slot = blockIdx.x;
    int tok = g_slot_token[slot];
    float4 v = ((const float4*)(x + (size_t)tok * DIM))[threadIdx.x];
    __half2 h0 = __floats2half2_rn(v.x, v.y);
    __half2 h1 = __floats2half2_rn(v.z, v.w);
    uint2 u; u.x = *(uint32_t*)&h0; u.y = *(uint32_t*)&h1;
    ((uint2*)(g_Xph + (size_t)slot * DIM))[threadIdx.x] = u;
}

// ---------------- GEMM1: H = silu(X W1^T)*(X W3^T) ----------------
// BM=128, BN=128, BK=64. 512 thr, 16 warps 4x4, warp tile 32x32.
// smem per stage: A 16K + B1 16K + B3 16K = 48K; 3 stages = 144K (dynamic).
// Row = 128B = 8 chunks of 16B, swizzle: chunk' = chunk ^ (row & 7).
#define S1_A  0
#define S1_B1 16384
#define S1_B3 32768
#define S1_STG 49152
#define S1_SMEM (3 * S1_STG)

__global__ __launch_bounds__(512, 1) void k_gemm1(const __half* __restrict__ W1g,
                                                  const __half* __restrict__ W3g) {
    extern __shared__ __align__(1024) uint8_t smem[];
    const int m0 = blockIdx.x * 128;
    if (m0 >= g_aoff[NEXP]) return;
    int e = 0;
    while (m0 >= g_aoff[e + 1]) e++;
    const int n0 = blockIdx.y * 128;
    const __half* W1 = W1g + (size_t)e * HID * DIM;
    const __half* W3 = W3g + (size_t)e * HID * DIM;

    const int tid = threadIdx.x, wid = tid >> 5, lane = tid & 31;
    const int wm = wid & 3, wn = wid >> 2;
    const uint32_t smemB = (uint32_t)__cvta_generic_to_shared(smem);

    // cp.async coords: 2 chunks per thread per matrix region
    int arow[2], ach[2];
    const __half* agp[2];
    const __half* b1gp[2];
    const __half* b3gp[2];
    uint32_t asw[2], bsw[2];
#pragma unroll
    for (int i = 0; i < 2; i++) {
        int idx = tid + i * 512;
        int row = idx >> 3, ch = idx & 7;
        arow[i] = row; ach[i] = ch;
        agp[i]  = g_Xph + (size_t)(m0 + row) * DIM + ch * 8;
        b1gp[i] = W1 + (size_t)(n0 + row) * DIM + ch * 8;
        b3gp[i] = W3 + (size_t)(n0 + row) * DIM + ch * 8;
        uint32_t off = (uint32_t)row * 128 + (uint32_t)((ch ^ (row & 7)) << 4);
        asw[i] = off; bsw[i] = off;
    }
    auto prefetch = [&](int t) {
        uint32_t st = smemB + (uint32_t)(t % 3) * S1_STG;
        const int k0 = t * 64;
#pragma unroll
        for (int i = 0; i < 2; i++) {
            cpa16(st + S1_A  + asw[i], agp[i]  + k0);
            cpa16(st + S1_B1 + bsw[i], b1gp[i] + k0);
            cpa16(st + S1_B3 + bsw[i], b3gp[i] + k0);
        }
    };

    // ldmatrix coords (fragment math identical to validated round-7 kernel)
    const int sub = lane >> 3, rin = lane & 7;
    const int asel = sub >> 1, bsel = sub & 1;
    uint32_t arow128[2], brow128[2];
#pragma unroll
    for (int mi = 0; mi < 2; mi++)
        arow128[mi] = (uint32_t)(wm * 32 + mi * 16 + (sub & 1) * 8 + rin) * 128;
#pragma unroll
    for (int nh = 0; nh < 2; nh++)
        brow128[nh] = (uint32_t)(wn * 32 + nh * 16 + (sub >> 1) * 8 + rin) * 128;

    float c1[2][4][4], c3[2][4][4];
#pragma unroll
    for (int mi = 0; mi < 2; mi++)
#pragma unroll
        for (int ni = 0; ni < 4; ni++)
#pragma unroll
            for (int q = 0; q < 4; q++) { c1[mi][ni][q] = 0.f; c3[mi][ni][q] = 0.f; }

    const int KT = DIM / 64;   // 16
    prefetch(0); cpa_commit();
    prefetch(1); cpa_commit();

#pragma unroll 1
    for (int t = 0; t < KT; t++) {
        cpa_wait<1>();
        __syncthreads();
        if (t + 2 < KT) prefetch(t + 2);
        cpa_commit();
        const uint32_t smb = smemB + (uint32_t)(t % 3) * S1_STG;
#pragma unroll
        for (int ks = 0; ks < 4; ks++) {
            const uint32_t axo = (uint32_t)(((2 * ks + asel) ^ rin) << 4);
            const uint32_t bxo = (uint32_t)(((2 * ks + bsel) ^ rin) << 4);
            uint32_t a[2][4], b1[2][4], b3[2][4];
#pragma unroll
            for (int mi = 0; mi < 2; mi++) ldm4(a[mi], smb + S1_A + arow128[mi] + axo);
#pragma unroll
            for (int nh = 0; nh < 2; nh++) {
                ldm4(b1[nh], smb + S1_B1 + brow128[nh] + bxo);
                ldm4(b3[nh], smb + S1_B3 + brow128[nh] + bxo);
            }
#pragma unroll
            for (int mi = 0; mi < 2; mi++)
#pragma unroll
                for (int ni = 0; ni < 4; ni++) {
                    mma16816(c1[mi][ni], a[mi], &b1[ni >> 1][2 * (ni & 1)]);
                    mma16816(c3[mi][ni], a[mi], &b3[ni >> 1][2 * (ni & 1)]);
                }
        }
    }

    // epilogue: h = silu(c1)*c3 -> fp16
    const int g = lane >> 2, tq = lane & 3;
#pragma unroll
    for (int mi = 0; mi < 2; mi++)
#pragma unroll
        for (int ni = 0; ni < 4; ni++) {
            int col = n0 + wn * 32 + ni * 8 + tq * 2;
#pragma unroll
            for (int h = 0; h < 2; h++) {
                int row = m0 + wm * 32 + mi * 16 + g + h * 8;
                float v0 = c1[mi][ni][h * 2], v1 = c1[mi][ni][h * 2 + 1];
                float s0 = v0 / (1.f + __expf(-v0)) * c3[mi][ni][h * 2];
                float s1 = v1 / (1.f + __expf(-v1)) * c3[mi][ni][h * 2 + 1];
                *(__half2*)(g_Hh + (size_t)row * HID + col) = __floats2half2_rn(s0, s1);
            }
        }
}

// ---------------- GEMM2: O = H W2^T ----------------
#define S2_A  0
#define S2_B  16384
#define S2_STG 32768
#define S2_SMEM (3 * S2_STG)

__global__ __launch_bounds__(512, 1) void k_gemm2(const __half* __restrict__ W2g) {
    extern __shared__ __align__(1024) uint8_t smem[];
    const int m0 = blockIdx.x * 128;
    if (m0 >= g_aoff[NEXP]) return;
    int e = 0;
    while (m0 >= g_aoff[e + 1]) e++;
    const int n0 = blockIdx.y * 128;
    const __half* W = W2g + (size_t)e * DIM * HID;

    const int tid = threadIdx.x, wid = tid >> 5, lane = tid & 31;
    const int wm = wid & 3, wn = wid >> 2;
    const uint32_t smemB = (uint32_t)__cvta_generic_to_shared(smem);

    const __half* agp[2];
    const __half* bgp[2];
    uint32_t sw[2];
#pragma unroll
    for (int i = 0; i < 2; i++) {
        int idx = tid + i * 512;
        int row = idx >> 3, ch = idx & 7;
        agp[i] = g_Hh + (size_t)(m0 + row) * HID + ch * 8;
        bgp[i] = W + (size_t)(n0 + row) * HID + ch * 8;
        sw[i] = (uint32_t)row * 128 + (uint32_t)((ch ^ (row & 7)) << 4);
    }
    auto prefetch = [&](int t) {
        uint32_t st = smemB + (uint32_t)(t % 3) * S2_STG;
        const int k0 = t * 64;
#pragma unroll
        for (int i = 0; i < 2; i++) {
            cpa16(st + S2_A + sw[i], agp[i] + k0);
            cpa16(st + S2_B + sw[i], bgp[i] + k0);
        }
    };

    const int sub = lane >> 3, rin = lane & 7;
    const int asel = sub >> 1, bsel = sub & 1;
    uint32_t arow128[2], brow128[2];
#pragma unroll
    for (int mi = 0; mi < 2; mi++)
        arow128[mi] = (uint32_t)(wm * 32 + mi * 16 + (sub & 1) * 8 + rin) * 128;
#pragma unroll
    for (int nh = 0; nh < 2; nh++)
        brow128[nh] = (uint32_t)(wn * 32 + nh * 16 + (sub >> 1) * 8 + rin) * 128;

    float c[2][4][4];
#pragma unroll
    for (int mi = 0; mi < 2; mi++)
#pragma unroll
        for (int ni = 0; ni < 4; ni++)
#pragma unroll
            for (int q = 0; q < 4; q++) c[mi][ni][q] = 0.f;

    const int KT = HID / 64;   // 44
    prefetch(0); cpa_commit();
    prefetch(1); cpa_commit();

#pragma unroll 1
    for (int t = 0; t < KT; t++) {
        cpa_wait<1>();
        __syncthreads();
        if (t + 2 < KT) prefetch(t + 2);
        cpa_commit();
        const uint32_t smb = smemB + (uint32_t)(t % 3) * S2_STG;
#pragma unroll
        for (int ks = 0; ks < 4; ks++) {
            const uint32_t axo = (uint32_t)(((2 * ks + asel) ^ rin) << 4);
            const uint32_t bxo = (uint32_t)(((2 * ks + bsel) ^ rin) << 4);
            uint32_t a[2][4], b[2][4];
#pragma unroll
            for (int mi = 0; mi < 2; mi++) ldm4(a[mi], smb + S2_A + arow128[mi] + axo);
#pragma unroll
            for (int nh = 0; nh < 2; nh++) ldm4(b[nh], smb + S2_B + brow128[nh] + bxo);
#pragma unroll
            for (int mi = 0; mi < 2; mi++)
#pragma unroll
                for (int ni = 0; ni < 4; ni++)
                    mma16816(c[mi][ni], a[mi], &b[ni >> 1][2 * (ni & 1)]);
        }
    }

    const int g = lane >> 2, tq = lane & 3;
#pragma unroll
    for (int mi = 0; mi < 2; mi++)
#pragma unroll
        for (int ni = 0; ni < 4; ni++) {
            int col = n0 + wn * 32 + ni * 8 + tq * 2;
#pragma unroll
            for (int h = 0; h < 2; h++) {
                int row = m0 + wm * 32 + mi * 16 + g + h * 8;
                float2 v = make_float2(c[mi][ni][h * 2], c[mi][ni][h * 2 + 1]);
                *(float2*)(g_O + (size_t)row * DIM + col) = v;
            }
        }
}

__global__ void k_combine(float* __restrict__ out) {
    int idx = blockIdx.x * blockDim.x + threadIdx.x;
    if (idx >= TOK * DIM / 4) return;
    int t = idx / (DIM / 4), d4 = idx % (DIM / 4);
    float w0 = g_ew[t*2], w1 = g_ew[t*2+1];
    int s0 = g_slot_of[t*2], s1 = g_slot_of[t*2+1];
    float4 a = *(const float4*)&g_O[(size_t)s0 * DIM + d4*4];
    float4 b = *(const float4*)&g_O[(size_t)s1 * DIM + d4*4];
    float4 r;
    r.x = w0*a.x + w1*b.x; r.y = w0*a.y + w1*b.y;
    r.z = w0*a.z + w1*b.z; r.w = w0*a.w + w1*b.w;
    ((float4*)out)[idx] = r;
}

extern "C" void kernel_launch(void* const* d_in, const int* in_sizes, int n_in,
                              void* d_out, int out_size) {
    const float* x  = (const float*)d_in[0];
    const float* gw = (const float*)d_in[1];
    const float* w1 = (const float*)d_in[2];
    const float* w2 = (const float*)d_in[3];
    const float* w3 = (const float*)d_in[4];
    float* out = (float*)d_out;

    cudaFuncSetAttribute(k_gemm1, cudaFuncAttributeMaxDynamicSharedMemorySize, S1_SMEM);
    cudaFuncSetAttribute(k_gemm2, cudaFuncAttributeMaxDynamicSharedMemorySize, S2_SMEM);

    __half *w1h, *w2h, *w3h;
    cudaGetSymbolAddress((void**)&w1h, g_W1h);
    cudaGetSymbolAddress((void**)&w2h, g_W2h);
    cudaGetSymbolAddress((void**)&w3h, g_W3h);

    const int N4 = WELEM / 4;   // 5767168
    k_cvt<<<(N4 + 255) / 256, 256>>>(w1, w1h, N4);
    k_cvt<<<(N4 + 255) / 256, 256>>>(w2, w2h, N4);
    k_cvt<<<(N4 + 255) / 256, 256>>>(w3, w3h, N4);

    k_zero<<<1, 32>>>();
    k_gate<<<TOK / 8, 256>>>(x, gw);
    k_scan<<<1, 256>>>();
    k_scatter<<<TOK / 256, 256>>>();
    k_permute<<<MAXSLOTS, 256>>>(x);
    k_gemm1<<<dim3(MTILES, HID / 128), 512, S1_SMEM>>>(w1h, w3h);
    k_gemm2<<<dim3(MTILES, DIM / 128), 512, S2_SMEM>>>(w2h);
    k_combine<<<(TOK * DIM / 4) / 256, 256>>>(out);
}